// round 8
// baseline (speedup 1.0000x reference)
#include <cuda_runtime.h>
#include <cuda_bf16.h>
#include <cstdint>
#include <cstddef>
#include <math.h>

// Problem constants
constexpr int B_  = 2;
constexpr int T_  = 2048;
constexpr int HID = 2048;
constexpr int NH  = 16;
constexpr int NKV = 4;
constexpr int HD  = 128;

// ---------------- scratch (static device arrays; no allocation) ----------------
__device__ float        g_Qf[(size_t)B_ * T_ * NH  * HD];
__device__ float        g_Kf[(size_t)B_ * T_ * NKV * HD];
__device__ float        g_Vf[(size_t)B_ * T_ * NKV * HD];
__device__ float        g_Octx[(size_t)B_ * T_ * NH * HD];
__device__ __nv_bfloat16 g_Qh[(size_t)B_ * NH  * T_ * HD];
__device__ __nv_bfloat16 g_Ql[(size_t)B_ * NH  * T_ * HD];
__device__ __nv_bfloat16 g_Kh[(size_t)B_ * NKV * T_ * HD];
__device__ __nv_bfloat16 g_Kl[(size_t)B_ * NKV * T_ * HD];
__device__ __nv_bfloat16 g_Vh[(size_t)B_ * NKV * T_ * HD];
__device__ __nv_bfloat16 g_Vl[(size_t)B_ * NKV * T_ * HD];

// ---------------- PTX helpers ----------------
__device__ __forceinline__ uint32_t smem_u32(const void* p) {
    return (uint32_t)__cvta_generic_to_shared(p);
}
__device__ __forceinline__ void ldsm4(uint32_t r[4], const void* p) {
    uint32_t a = smem_u32(p);
    asm volatile("ldmatrix.sync.aligned.m8n8.x4.shared.b16 {%0,%1,%2,%3}, [%4];"
                 : "=r"(r[0]), "=r"(r[1]), "=r"(r[2]), "=r"(r[3]) : "r"(a));
}
__device__ __forceinline__ void ldsm4t(uint32_t r[4], const void* p) {
    uint32_t a = smem_u32(p);
    asm volatile("ldmatrix.sync.aligned.m8n8.x4.trans.shared.b16 {%0,%1,%2,%3}, [%4];"
                 : "=r"(r[0]), "=r"(r[1]), "=r"(r[2]), "=r"(r[3]) : "r"(a));
}
__device__ __forceinline__ void mma_bf16(float c[4], const uint32_t a[4], uint32_t b0, uint32_t b1) {
    asm volatile("mma.sync.aligned.m16n8k16.row.col.f32.bf16.bf16.f32 "
                 "{%0,%1,%2,%3}, {%4,%5,%6,%7}, {%8,%9}, {%0,%1,%2,%3};"
                 : "+f"(c[0]), "+f"(c[1]), "+f"(c[2]), "+f"(c[3])
                 : "r"(a[0]), "r"(a[1]), "r"(a[2]), "r"(a[3]), "r"(b0), "r"(b1));
}
__device__ __forceinline__ void cpasync16(uint32_t saddr, const void* g) {
    asm volatile("cp.async.cg.shared.global [%0], [%1], 16;" :: "r"(saddr), "l"(g));
}
__device__ __forceinline__ void cpcommit() { asm volatile("cp.async.commit_group;"); }
template <int N> __device__ __forceinline__ void cpwait() {
    asm volatile("cp.async.wait_group %0;" :: "n"(N));
}
__device__ __forceinline__ void split2(float a, float b, uint32_t& hv, uint32_t& lv) {
    __nv_bfloat162 h = __floats2bfloat162_rn(a, b);
    float2 f = __bfloat1622float2(h);
    __nv_bfloat162 l = __floats2bfloat162_rn(a - f.x, b - f.y);
    hv = *reinterpret_cast<uint32_t*>(&h);
    lv = *reinterpret_cast<uint32_t*>(&l);
}
__device__ __forceinline__ void split_store4(float4 v, __nv_bfloat16* hi, __nv_bfloat16* lo) {
    uint32_t h0, l0, h1, l1;
    split2(v.x, v.y, h0, l0);
    split2(v.z, v.w, h1, l1);
    *reinterpret_cast<uint2*>(hi) = make_uint2(h0, h1);
    *reinterpret_cast<uint2*>(lo) = make_uint2(l0, l1);
}

// =====================================================================
// GEMM: C[M,N] = A[M,K] @ B[K,N], fp32 in/out, bf16x3 split tensor-core
// CTA tile 128x128x32, 256 threads (8 warps 4x2), warp tile 32x64.
// 2 CTAs per SM (regs capped at 128, smem 75.8KB). Two smem stages,
// one barrier per k-tile. blockIdx.z selects (Bm,C)/(Bm2,C2) for K+V fusion.
// =====================================================================
constexpr int SA_ST = 40;    // sA row stride (32+8 halves)
constexpr int SB_ST = 136;   // sB row stride (128+8 halves)
constexpr int SA_SZ = 128 * SA_ST;          // 5120
constexpr int SB_SZ = 32 * SB_ST;           // 4352
constexpr int ST_SZ = 2 * SA_SZ + 2 * SB_SZ;   // halves per stage = 18944
constexpr int GEMM_SMEM_BYTES = 2 * ST_SZ * 2; // 75776 B

__global__ __launch_bounds__(256, 2) void gemm_bf16x3(
    const float* __restrict__ A, const float* __restrict__ Bm, float* __restrict__ C,
    const float* __restrict__ Bm2, float* __restrict__ C2,
    int M, int N, int K)
{
    extern __shared__ __nv_bfloat16 gs[];
    if (blockIdx.z) { Bm = Bm2; C = C2; }

    const int tid  = threadIdx.x;
    const int lane = tid & 31;
    const int wid  = tid >> 5;                 // 0..7
    const int bm   = blockIdx.y, bn = blockIdx.x;
    const int wm   = (wid >> 1) * 32;
    const int wn   = (wid & 1) * 64;

    const float* Ab = A + (size_t)bm * 128 * K;
    const float* Bb = Bm + (size_t)bn * 128;

    float acc[2][8][4] = {};
    float4 ra[4], rb[4];

    auto gload = [&](int k0) {
#pragma unroll
        for (int i = 0; i < 4; i++) {
            int idx = i * 256 + tid;            // 1024 chunks of 4 f32, A 128x32
            int r = idx >> 3, c4 = idx & 7;
            ra[i] = *(const float4*)(Ab + (size_t)r * K + k0 + c4 * 4);
        }
#pragma unroll
        for (int i = 0; i < 4; i++) {
            int idx = i * 256 + tid;            // B 32x128
            int r = idx >> 5, c4 = idx & 31;
            rb[i] = *(const float4*)(Bb + (size_t)(k0 + r) * N + c4 * 4);
        }
    };
    auto sstore = [&](int s) {
        __nv_bfloat16* sA0 = gs + s * ST_SZ;
        __nv_bfloat16* sA1 = sA0 + SA_SZ;
        __nv_bfloat16* sB0 = sA0 + 2 * SA_SZ;
        __nv_bfloat16* sB1 = sB0 + SB_SZ;
#pragma unroll
        for (int i = 0; i < 4; i++) {
            int idx = i * 256 + tid;
            int r = idx >> 3, c = (idx & 7) * 4;
            split_store4(ra[i], sA0 + r * SA_ST + c, sA1 + r * SA_ST + c);
        }
#pragma unroll
        for (int i = 0; i < 4; i++) {
            int idx = i * 256 + tid;
            int r = idx >> 5, c = (idx & 31) * 4;
            split_store4(rb[i], sB0 + r * SB_ST + c, sB1 + r * SB_ST + c);
        }
    };

    gload(0);
    sstore(0);
    __syncthreads();

    const int nk = K / 32;
    for (int kt = 0; kt < nk; kt++) {
        const int s = kt & 1;
        if (kt + 1 < nk) gload((kt + 1) * 32);

        const __nv_bfloat16* sA0 = gs + s * ST_SZ;
        const __nv_bfloat16* sA1 = sA0 + SA_SZ;
        const __nv_bfloat16* sB0 = sA0 + 2 * SA_SZ;
        const __nv_bfloat16* sB1 = sB0 + SB_SZ;

#pragma unroll
        for (int ks = 0; ks < 2; ks++) {
            const int colA = ks * 16 + ((lane >> 4) << 3);
            uint32_t af0[2][4], af1[2][4];
#pragma unroll
            for (int mf = 0; mf < 2; mf++) {
                int row = wm + mf * 16 + (lane & 15);
                ldsm4(af0[mf], sA0 + row * SA_ST + colA);
                ldsm4(af1[mf], sA1 + row * SA_ST + colA);
            }
            const int rowB = ks * 16 + (lane & 15);
#pragma unroll
            for (int nf2 = 0; nf2 < 4; nf2++) {
                const int colB = wn + nf2 * 16 + ((lane >> 4) << 3);
                uint32_t bh[4], bl[4];
                ldsm4t(bh, sB0 + rowB * SB_ST + colB);
                ldsm4t(bl, sB1 + rowB * SB_ST + colB);
#pragma unroll
                for (int mf = 0; mf < 2; mf++) {
#pragma unroll
                    for (int sub = 0; sub < 2; sub++) {
                        const int nf = nf2 * 2 + sub;
                        mma_bf16(acc[mf][nf], af0[mf], bh[sub * 2], bh[sub * 2 + 1]);
                        mma_bf16(acc[mf][nf], af0[mf], bl[sub * 2], bl[sub * 2 + 1]);
                        mma_bf16(acc[mf][nf], af1[mf], bh[sub * 2], bh[sub * 2 + 1]);
                    }
                }
            }
        }
        if (kt + 1 < nk) sstore(s ^ 1);
        __syncthreads();
    }

#pragma unroll
    for (int mf = 0; mf < 2; mf++) {
        int r0 = bm * 128 + wm + mf * 16 + (lane >> 2);
#pragma unroll
        for (int nf = 0; nf < 8; nf++) {
            int c = bn * 128 + wn + nf * 8 + (lane & 3) * 2;
            *(float2*)(C + (size_t)r0 * N + c)       = make_float2(acc[mf][nf][0], acc[mf][nf][1]);
            *(float2*)(C + (size_t)(r0 + 8) * N + c) = make_float2(acc[mf][nf][2], acc[mf][nf][3]);
        }
    }
}

// =====================================================================
// Fused RoPE + scale + bf16 hi/lo split + relayout (Q, K, V in one launch)
// =====================================================================
constexpr int NQE = B_ * T_ * NH * HD;    // 8388608
constexpr int NKE = B_ * T_ * NKV * HD;   // 2097152

__device__ __forceinline__ void rope_one(
    const float* __restrict__ src, const float* __restrict__ cosb, const float* __restrict__ sinb,
    __nv_bfloat16* __restrict__ dh, __nv_bfloat16* __restrict__ dl,
    int idx, int H, int do_rope, float scale)
{
    int d    = idx & 127;
    int rest = idx >> 7;
    int h    = rest % H;
    int bt   = rest / H;
    int t    = bt & (T_ - 1);
    int b    = bt >> 11;

    float v = src[idx];
    float o;
    if (do_rope) {
        int dd = d & 63;
        float c = cosb[t * 64 + dd], s = sinb[t * 64 + dd];
        if (d < 64) { float v2 = src[idx + 64]; o = v * c - v2 * s; }
        else        { float v1 = src[idx - 64]; o = v * c + v1 * s; }
    } else {
        o = v;
    }
    o *= scale;
    __nv_bfloat16 hh = __float2bfloat16(o);
    size_t di = (((size_t)(b * H + h)) * T_ + t) * HD + d;
    dh[di] = hh;
    dl[di] = __float2bfloat16(o - __bfloat162float(hh));
}

__global__ void rope_all(const float* __restrict__ Qf, const float* __restrict__ Kf,
                         const float* __restrict__ Vf,
                         const float* __restrict__ cosb, const float* __restrict__ sinb,
                         __nv_bfloat16* __restrict__ Qh, __nv_bfloat16* __restrict__ Ql,
                         __nv_bfloat16* __restrict__ Kh, __nv_bfloat16* __restrict__ Kl,
                         __nv_bfloat16* __restrict__ Vh, __nv_bfloat16* __restrict__ Vl,
                         float qsc)
{
    int idx = blockIdx.x * 256 + threadIdx.x;
    if (idx < NQE) {
        rope_one(Qf, cosb, sinb, Qh, Ql, idx, NH, 1, qsc);
    } else if (idx < NQE + NKE) {
        rope_one(Kf, cosb, sinb, Kh, Kl, idx - NQE, NKV, 1, 1.0f);
    } else {
        rope_one(Vf, cosb, sinb, Vh, Vl, idx - NQE - NKE, NKV, 0, 1.0f);
    }
}

// =====================================================================
// Flash attention (causal, GQA). Br=64 (4 warps x 16 rows), Bc=64,
// single KV buffer, 2 CTAs per SM (smem 104.4KB, 240 regs x 128 thr).
// Q,K,V pre-split bf16 hi/lo in [BH, T, 128]. Output fp32 [B*T, 2048].
// =====================================================================
constexpr int AS       = 136;
constexpr int Q_H_OFF  = 0;
constexpr int Q_L_OFF  = 64 * AS;
constexpr int KV_OFF   = 2 * 64 * AS;
constexpr int ATTN_SMEM_BYTES = (2 * 64 * AS + 4 * 64 * AS) * 2;   // 104448

__global__ __launch_bounds__(128, 2) void attn_kernel(
    const __nv_bfloat16* __restrict__ Qh, const __nv_bfloat16* __restrict__ Ql,
    const __nv_bfloat16* __restrict__ Kh, const __nv_bfloat16* __restrict__ Kl,
    const __nv_bfloat16* __restrict__ Vh, const __nv_bfloat16* __restrict__ Vl,
    float* __restrict__ O)
{
    extern __shared__ __nv_bfloat16 sm[];
    const int tid  = threadIdx.x;
    const int lane = tid & 31;
    const int wid  = tid >> 5;                 // 0..3
    const int bh   = blockIdx.y;
    const int b    = bh >> 4, h = bh & 15;
    const int qi   = (int)gridDim.x - 1 - (int)blockIdx.x;   // heavy first
    const int qbase = qi * 64;
    const int kvi  = b * NKV + (h >> 2);

    const __nv_bfloat16* qh_g = Qh + ((size_t)bh * T_ + qbase) * HD;
    const __nv_bfloat16* ql_g = Ql + ((size_t)bh * T_ + qbase) * HD;
    const __nv_bfloat16* ks_g[4] = {
        Kh + (size_t)kvi * T_ * HD, Kl + (size_t)kvi * T_ * HD,
        Vh + (size_t)kvi * T_ * HD, Vl + (size_t)kvi * T_ * HD
    };

    // Q tile: 64 rows x 128 halves x 2 splits = 2048 x 16B chunks
#pragma unroll
    for (int i = 0; i < 16; i++) {
        int c = i * 128 + tid;
        int split = c >> 10, cc = c & 1023;
        int row = cc >> 4, ch = cc & 15;
        const __nv_bfloat16* src = (split ? ql_g : qh_g) + row * HD + ch * 8;
        cpasync16(smem_u32(sm + (split ? Q_L_OFF : Q_H_OFF) + row * AS + ch * 8), src);
    }
    cpcommit();

    auto loadKV = [&](int j) {
        size_t gb = (size_t)j * 64 * HD;
#pragma unroll
        for (int i = 0; i < 32; i++) {
            int c = i * 128 + tid;
            int which = c >> 10, cc = c & 1023;
            int row = cc >> 4, ch = cc & 15;
            cpasync16(smem_u32(sm + KV_OFF + which * (64 * AS) + row * AS + ch * 8),
                      ks_g[which] + gb + row * HD + ch * 8);
        }
        cpcommit();
    };

    float m0 = -1e30f, m1 = -1e30f, l0 = 0.f, l1 = 0.f;
    float o[16][4];
#pragma unroll
    for (int i = 0; i < 16; i++)
#pragma unroll
        for (int j = 0; j < 4; j++) o[i][j] = 0.f;

    const int nj = qi + 1;
    const int rowbase = qbase + wid * 16;

    for (int j = 0; j < nj; j++) {
        loadKV(j);
        cpwait<0>();
        __syncthreads();

        // ---- S = Q K^T (exp2 domain) ----
        float sacc[8][4];
#pragma unroll
        for (int i = 0; i < 8; i++)
#pragma unroll
            for (int jj = 0; jj < 4; jj++) sacc[i][jj] = 0.f;

#pragma unroll
        for (int ks = 0; ks < 8; ks++) {
            uint32_t qa[2][4];
            {
                int row = wid * 16 + (lane & 15);
                int col = ks * 16 + ((lane >> 4) << 3);
                ldsm4(qa[0], sm + Q_H_OFF + row * AS + col);
                ldsm4(qa[1], sm + Q_L_OFF + row * AS + col);
            }
#pragma unroll
            for (int nf2 = 0; nf2 < 4; nf2++) {
                uint32_t kh4[4], kl4[4];
                int krow = nf2 * 16 + (lane & 15);
                int kcol = ks * 16 + ((lane >> 4) << 3);
                ldsm4(kh4, sm + KV_OFF + krow * AS + kcol);
                ldsm4(kl4, sm + KV_OFF + 64 * AS + krow * AS + kcol);
                mma_bf16(sacc[2 * nf2],     qa[0], kh4[0], kh4[2]);
                mma_bf16(sacc[2 * nf2],     qa[0], kl4[0], kl4[2]);
                mma_bf16(sacc[2 * nf2],     qa[1], kh4[0], kh4[2]);
                mma_bf16(sacc[2 * nf2 + 1], qa[0], kh4[1], kh4[3]);
                mma_bf16(sacc[2 * nf2 + 1], qa[0], kl4[1], kl4[3]);
                mma_bf16(sacc[2 * nf2 + 1], qa[1], kh4[1], kh4[3]);
            }
        }

        // ---- causal mask (diagonal tile only) ----
        const int kvb = j * 64;
        if (kvb + 63 > rowbase) {
            int r0 = rowbase + (lane >> 2), r1 = r0 + 8;
#pragma unroll
            for (int nf = 0; nf < 8; nf++) {
                int c0 = kvb + nf * 8 + (lane & 3) * 2;
                if (c0 > r0)     sacc[nf][0] = -1e30f;
                if (c0 + 1 > r0) sacc[nf][1] = -1e30f;
                if (c0 > r1)     sacc[nf][2] = -1e30f;
                if (c0 + 1 > r1) sacc[nf][3] = -1e30f;
            }
        }

        // ---- online softmax (base 2) ----
        float rm0 = -1e30f, rm1 = -1e30f;
#pragma unroll
        for (int nf = 0; nf < 8; nf++) {
            rm0 = fmaxf(rm0, fmaxf(sacc[nf][0], sacc[nf][1]));
            rm1 = fmaxf(rm1, fmaxf(sacc[nf][2], sacc[nf][3]));
        }
        rm0 = fmaxf(rm0, __shfl_xor_sync(0xffffffffu, rm0, 1));
        rm0 = fmaxf(rm0, __shfl_xor_sync(0xffffffffu, rm0, 2));
        rm1 = fmaxf(rm1, __shfl_xor_sync(0xffffffffu, rm1, 1));
        rm1 = fmaxf(rm1, __shfl_xor_sync(0xffffffffu, rm1, 2));
        float mn0 = fmaxf(m0, rm0), mn1 = fmaxf(m1, rm1);
        float corr0 = exp2f(m0 - mn0), corr1 = exp2f(m1 - mn1);
        m0 = mn0; m1 = mn1;

        float rs0 = 0.f, rs1 = 0.f;
#pragma unroll
        for (int nf = 0; nf < 8; nf++) {
            float p0 = exp2f(sacc[nf][0] - mn0);
            float p1 = exp2f(sacc[nf][1] - mn0);
            float p2 = exp2f(sacc[nf][2] - mn1);
            float p3 = exp2f(sacc[nf][3] - mn1);
            sacc[nf][0] = p0; sacc[nf][1] = p1; sacc[nf][2] = p2; sacc[nf][3] = p3;
            rs0 += p0 + p1; rs1 += p2 + p3;
        }
        l0 = l0 * corr0 + rs0;
        l1 = l1 * corr1 + rs1;
        // skip o-rescale when running max unchanged (common after early tiles)
        if (__any_sync(0xffffffffu, (corr0 != 1.f) || (corr1 != 1.f))) {
#pragma unroll
            for (int df = 0; df < 16; df++) {
                o[df][0] *= corr0; o[df][1] *= corr0;
                o[df][2] *= corr1; o[df][3] *= corr1;
            }
        }

        // ---- pack P into bf16 hi/lo A-fragments ----
        uint32_t ph[4][4], pl[4][4];
#pragma unroll
        for (int kk = 0; kk < 4; kk++) {
            const float* A0 = sacc[2 * kk];
            const float* A1 = sacc[2 * kk + 1];
            split2(A0[0], A0[1], ph[kk][0], pl[kk][0]);
            split2(A0[2], A0[3], ph[kk][1], pl[kk][1]);
            split2(A1[0], A1[1], ph[kk][2], pl[kk][2]);
            split2(A1[2], A1[3], ph[kk][3], pl[kk][3]);
        }

        // ---- O += P V ----
        const int vb = KV_OFF + 2 * 64 * AS;
#pragma unroll
        for (int kk = 0; kk < 4; kk++) {
#pragma unroll
            for (int nf2 = 0; nf2 < 8; nf2++) {
                uint32_t vh4[4], vl4[4];
                int vrow = kk * 16 + (lane & 15);
                int vcol = nf2 * 16 + ((lane >> 4) << 3);
                ldsm4t(vh4, sm + vb + vrow * AS + vcol);
                ldsm4t(vl4, sm + vb + 64 * AS + vrow * AS + vcol);
                mma_bf16(o[2 * nf2],     ph[kk], vh4[0], vh4[1]);
                mma_bf16(o[2 * nf2],     ph[kk], vl4[0], vl4[1]);
                mma_bf16(o[2 * nf2],     pl[kk], vh4[0], vh4[1]);
                mma_bf16(o[2 * nf2 + 1], ph[kk], vh4[2], vh4[3]);
                mma_bf16(o[2 * nf2 + 1], ph[kk], vl4[2], vl4[3]);
                mma_bf16(o[2 * nf2 + 1], pl[kk], vh4[2], vh4[3]);
            }
        }
        __syncthreads();   // all reads done before next tile's cp.async overwrites
    }

    // ---- finalize ----
    l0 += __shfl_xor_sync(0xffffffffu, l0, 1);
    l0 += __shfl_xor_sync(0xffffffffu, l0, 2);
    l1 += __shfl_xor_sync(0xffffffffu, l1, 1);
    l1 += __shfl_xor_sync(0xffffffffu, l1, 2);
    float inv0 = 1.f / l0, inv1 = 1.f / l1;

    int r0 = rowbase + (lane >> 2);
    size_t base0 = ((size_t)b * T_ + r0) * HID + h * HD + (lane & 3) * 2;
    size_t base1 = base0 + (size_t)8 * HID;
#pragma unroll
    for (int df = 0; df < 16; df++) {
        *(float2*)(O + base0 + df * 8) = make_float2(o[df][0] * inv0, o[df][1] * inv0);
        *(float2*)(O + base1 + df * 8) = make_float2(o[df][2] * inv1, o[df][3] * inv1);
    }
}

// =====================================================================
// host launcher
// =====================================================================
extern "C" void kernel_launch(void* const* d_in, const int* in_sizes, int n_in,
                              void* d_out, int out_size)
{
    const float* x    = (const float*)d_in[0];
    const float* cosb = (const float*)d_in[1];
    const float* sinb = (const float*)d_in[2];
    const float* wq   = (const float*)d_in[3];
    const float* wk   = (const float*)d_in[4];
    const float* wv   = (const float*)d_in[5];
    const float* wo   = (const float*)d_in[6];

    float *Qf, *Kf, *Vf, *Octx;
    __nv_bfloat16 *Qh, *Ql, *Kh, *Kl, *Vh, *Vl;
    cudaGetSymbolAddress((void**)&Qf, g_Qf);
    cudaGetSymbolAddress((void**)&Kf, g_Kf);
    cudaGetSymbolAddress((void**)&Vf, g_Vf);
    cudaGetSymbolAddress((void**)&Octx, g_Octx);
    cudaGetSymbolAddress((void**)&Qh, g_Qh);
    cudaGetSymbolAddress((void**)&Ql, g_Ql);
    cudaGetSymbolAddress((void**)&Kh, g_Kh);
    cudaGetSymbolAddress((void**)&Kl, g_Kl);
    cudaGetSymbolAddress((void**)&Vh, g_Vh);
    cudaGetSymbolAddress((void**)&Vl, g_Vl);

    cudaFuncSetAttribute(attn_kernel, cudaFuncAttributeMaxDynamicSharedMemorySize,
                         ATTN_SMEM_BYTES);
    cudaFuncSetAttribute(gemm_bf16x3, cudaFuncAttributeMaxDynamicSharedMemorySize,
                         GEMM_SMEM_BYTES);

    const int M = B_ * T_;  // 4096
    float qsc = (1.0f / sqrtf((float)HD)) * 1.4426950408889634f;

    // launch order: attn at launch index 3 (ncu capture slot)
    gemm_bf16x3<<<dim3((NKV * HD) / 128, M / 128, 2), 256, GEMM_SMEM_BYTES>>>(
        x, wk, Kf, wv, Vf, M, NKV * HD, HID);                                    // 0: K+V fused
    gemm_bf16x3<<<dim3(HID / 128, M / 128, 1), 256, GEMM_SMEM_BYTES>>>(
        x, wq, Qf, wq, Qf, M, HID, HID);                                         // 1: Q
    rope_all<<<(NQE + 2 * NKE) / 256, 256>>>(Qf, Kf, Vf, cosb, sinb,
                                             Qh, Ql, Kh, Kl, Vh, Vl, qsc);       // 2
    attn_kernel<<<dim3(T_ / 64, B_ * NH), 128, ATTN_SMEM_BYTES>>>(
        Qh, Ql, Kh, Kl, Vh, Vl, Octx);                                           // 3  <- ncu
    gemm_bf16x3<<<dim3(HID / 128, M / 128, 1), 256, GEMM_SMEM_BYTES>>>(
        Octx, wo, (float*)d_out, wo, (float*)d_out, M, HID, HID);                // 4: O
}

// round 9
// speedup vs baseline: 1.0352x; 1.0352x over previous
#include <cuda_runtime.h>
#include <cuda_bf16.h>
#include <cstdint>
#include <cstddef>
#include <math.h>

// Problem constants
constexpr int B_  = 2;
constexpr int T_  = 2048;
constexpr int HID = 2048;
constexpr int NH  = 16;
constexpr int NKV = 4;
constexpr int HD  = 128;

// ---------------- scratch (static device arrays; no allocation) ----------------
__device__ float        g_Qf[(size_t)B_ * T_ * NH  * HD];
__device__ float        g_Kf[(size_t)B_ * T_ * NKV * HD];
__device__ float        g_Vf[(size_t)B_ * T_ * NKV * HD];
__device__ float        g_Octx[(size_t)B_ * T_ * NH * HD];
__device__ __nv_bfloat16 g_Qh[(size_t)B_ * NH  * T_ * HD];
__device__ __nv_bfloat16 g_Ql[(size_t)B_ * NH  * T_ * HD];
__device__ __nv_bfloat16 g_Kh[(size_t)B_ * NKV * T_ * HD];
__device__ __nv_bfloat16 g_Kl[(size_t)B_ * NKV * T_ * HD];
__device__ __nv_bfloat16 g_Vh[(size_t)B_ * NKV * T_ * HD];
__device__ __nv_bfloat16 g_Vl[(size_t)B_ * NKV * T_ * HD];

// ---------------- PTX helpers ----------------
__device__ __forceinline__ uint32_t smem_u32(const void* p) {
    return (uint32_t)__cvta_generic_to_shared(p);
}
__device__ __forceinline__ void ldsm4(uint32_t r[4], const void* p) {
    uint32_t a = smem_u32(p);
    asm volatile("ldmatrix.sync.aligned.m8n8.x4.shared.b16 {%0,%1,%2,%3}, [%4];"
                 : "=r"(r[0]), "=r"(r[1]), "=r"(r[2]), "=r"(r[3]) : "r"(a));
}
__device__ __forceinline__ void ldsm4t(uint32_t r[4], const void* p) {
    uint32_t a = smem_u32(p);
    asm volatile("ldmatrix.sync.aligned.m8n8.x4.trans.shared.b16 {%0,%1,%2,%3}, [%4];"
                 : "=r"(r[0]), "=r"(r[1]), "=r"(r[2]), "=r"(r[3]) : "r"(a));
}
__device__ __forceinline__ void mma_bf16(float c[4], const uint32_t a[4], uint32_t b0, uint32_t b1) {
    asm volatile("mma.sync.aligned.m16n8k16.row.col.f32.bf16.bf16.f32 "
                 "{%0,%1,%2,%3}, {%4,%5,%6,%7}, {%8,%9}, {%0,%1,%2,%3};"
                 : "+f"(c[0]), "+f"(c[1]), "+f"(c[2]), "+f"(c[3])
                 : "r"(a[0]), "r"(a[1]), "r"(a[2]), "r"(a[3]), "r"(b0), "r"(b1));
}
__device__ __forceinline__ void cpasync16(uint32_t saddr, const void* g) {
    asm volatile("cp.async.cg.shared.global [%0], [%1], 16;" :: "r"(saddr), "l"(g));
}
__device__ __forceinline__ void cpcommit() { asm volatile("cp.async.commit_group;"); }
template <int N> __device__ __forceinline__ void cpwait() {
    asm volatile("cp.async.wait_group %0;" :: "n"(N));
}
__device__ __forceinline__ void split2(float a, float b, uint32_t& hv, uint32_t& lv) {
    __nv_bfloat162 h = __floats2bfloat162_rn(a, b);
    float2 f = __bfloat1622float2(h);
    __nv_bfloat162 l = __floats2bfloat162_rn(a - f.x, b - f.y);
    hv = *reinterpret_cast<uint32_t*>(&h);
    lv = *reinterpret_cast<uint32_t*>(&l);
}
__device__ __forceinline__ void split_store4(float4 v, __nv_bfloat16* hi, __nv_bfloat16* lo) {
    uint32_t h0, l0, h1, l1;
    split2(v.x, v.y, h0, l0);
    split2(v.z, v.w, h1, l1);
    *reinterpret_cast<uint2*>(hi) = make_uint2(h0, h1);
    *reinterpret_cast<uint2*>(lo) = make_uint2(l0, l1);
}

// =====================================================================
// GEMM: C[M,N] = A[M,K] @ B[K,N], fp32 in/out, bf16x3 split tensor-core
// CTA tile 128x256x32, 512 threads (16 warps 4x4), warp tile 32x64.
// Two smem stages, one barrier per k-tile. mma issued TERM-MAJOR per nf2
// so each accumulator's 3 split terms are spaced by 4 independent mmas
// (breaks dependent HMMA chains; per-acc order hh,hl,lh preserved).
// blockIdx.z selects (Bm,C)/(Bm2,C2) so K and V projections fuse.
// =====================================================================
constexpr int SA_ST = 40;    // sA row stride (32+8 halves)
constexpr int SB_ST = 264;   // sB row stride (256+8 halves)
constexpr int SA_SZ = 128 * SA_ST;
constexpr int SB_SZ = 32 * SB_ST;
constexpr int ST_SZ = 2 * SA_SZ + 2 * SB_SZ;               // halves per stage
constexpr int GEMM_SMEM_BYTES = 2 * ST_SZ * 2;             // 108544 B

__global__ __launch_bounds__(512, 1) void gemm_bf16x3(
    const float* __restrict__ A, const float* __restrict__ Bm, float* __restrict__ C,
    const float* __restrict__ Bm2, float* __restrict__ C2,
    int M, int N, int K)
{
    extern __shared__ __nv_bfloat16 gs[];
    if (blockIdx.z) { Bm = Bm2; C = C2; }

    const int tid  = threadIdx.x;
    const int lane = tid & 31;
    const int wid  = tid >> 5;                 // 0..15
    const int bm   = blockIdx.y, bn = blockIdx.x;
    const int wm   = (wid >> 2) * 32;
    const int wn   = (wid & 3) * 64;

    const float* Ab = A + (size_t)bm * 128 * K;
    const float* Bb = Bm + (size_t)bn * 256;

    float acc[2][8][4] = {};
    float4 ra[2], rb[4];

    auto gload = [&](int k0) {
#pragma unroll
        for (int i = 0; i < 2; i++) {
            int idx = i * 512 + tid;
            int r = idx >> 3, c4 = idx & 7;
            ra[i] = *(const float4*)(Ab + (size_t)r * K + k0 + c4 * 4);
        }
#pragma unroll
        for (int i = 0; i < 4; i++) {
            int idx = i * 512 + tid;
            int r = idx >> 6, c4 = idx & 63;
            rb[i] = *(const float4*)(Bb + (size_t)(k0 + r) * N + c4 * 4);
        }
    };
    auto sstore = [&](int s) {
        __nv_bfloat16* sA0 = gs + s * ST_SZ;
        __nv_bfloat16* sA1 = sA0 + SA_SZ;
        __nv_bfloat16* sB0 = sA0 + 2 * SA_SZ;
        __nv_bfloat16* sB1 = sB0 + SB_SZ;
#pragma unroll
        for (int i = 0; i < 2; i++) {
            int idx = i * 512 + tid;
            int r = idx >> 3, c = (idx & 7) * 4;
            split_store4(ra[i], sA0 + r * SA_ST + c, sA1 + r * SA_ST + c);
        }
#pragma unroll
        for (int i = 0; i < 4; i++) {
            int idx = i * 512 + tid;
            int r = idx >> 6, c = (idx & 63) * 4;
            split_store4(rb[i], sB0 + r * SB_ST + c, sB1 + r * SB_ST + c);
        }
    };

    gload(0);
    sstore(0);
    __syncthreads();

    const int nk = K / 32;
    for (int kt = 0; kt < nk; kt++) {
        const int s = kt & 1;
        if (kt + 1 < nk) gload((kt + 1) * 32);

        const __nv_bfloat16* sA0 = gs + s * ST_SZ;
        const __nv_bfloat16* sA1 = sA0 + SA_SZ;
        const __nv_bfloat16* sB0 = sA0 + 2 * SA_SZ;
        const __nv_bfloat16* sB1 = sB0 + SB_SZ;

#pragma unroll
        for (int ks = 0; ks < 2; ks++) {
            const int colA = ks * 16 + ((lane >> 4) << 3);
            uint32_t af0[2][4], af1[2][4];
#pragma unroll
            for (int mf = 0; mf < 2; mf++) {
                int row = wm + mf * 16 + (lane & 15);
                ldsm4(af0[mf], sA0 + row * SA_ST + colA);
                ldsm4(af1[mf], sA1 + row * SA_ST + colA);
            }
            const int rowB = ks * 16 + (lane & 15);
#pragma unroll
            for (int nf2 = 0; nf2 < 4; nf2++) {
                const int colB = wn + nf2 * 16 + ((lane >> 4) << 3);
                uint32_t bh[4], bl[4];
                ldsm4t(bh, sB0 + rowB * SB_ST + colB);
                ldsm4t(bl, sB1 + rowB * SB_ST + colB);
                // term-major: 4 independent mmas between chain hits
#pragma unroll
                for (int mf = 0; mf < 2; mf++)
#pragma unroll
                    for (int sub = 0; sub < 2; sub++)
                        mma_bf16(acc[mf][nf2 * 2 + sub], af0[mf], bh[sub * 2], bh[sub * 2 + 1]);
#pragma unroll
                for (int mf = 0; mf < 2; mf++)
#pragma unroll
                    for (int sub = 0; sub < 2; sub++)
                        mma_bf16(acc[mf][nf2 * 2 + sub], af0[mf], bl[sub * 2], bl[sub * 2 + 1]);
#pragma unroll
                for (int mf = 0; mf < 2; mf++)
#pragma unroll
                    for (int sub = 0; sub < 2; sub++)
                        mma_bf16(acc[mf][nf2 * 2 + sub], af1[mf], bh[sub * 2], bh[sub * 2 + 1]);
            }
        }
        if (kt + 1 < nk) sstore(s ^ 1);
        __syncthreads();
    }

#pragma unroll
    for (int mf = 0; mf < 2; mf++) {
        int r0 = bm * 128 + wm + mf * 16 + (lane >> 2);
#pragma unroll
        for (int nf = 0; nf < 8; nf++) {
            int c = bn * 256 + wn + nf * 8 + (lane & 3) * 2;
            *(float2*)(C + (size_t)r0 * N + c)       = make_float2(acc[mf][nf][0], acc[mf][nf][1]);
            *(float2*)(C + (size_t)(r0 + 8) * N + c) = make_float2(acc[mf][nf][2], acc[mf][nf][3]);
        }
    }
}

// =====================================================================
// Fused RoPE + scale + bf16 hi/lo split + relayout (Q, K, V in one launch)
// =====================================================================
constexpr int NQE = B_ * T_ * NH * HD;    // 8388608
constexpr int NKE = B_ * T_ * NKV * HD;   // 2097152

__device__ __forceinline__ void rope_one(
    const float* __restrict__ src, const float* __restrict__ cosb, const float* __restrict__ sinb,
    __nv_bfloat16* __restrict__ dh, __nv_bfloat16* __restrict__ dl,
    int idx, int H, int do_rope, float scale)
{
    int d    = idx & 127;
    int rest = idx >> 7;
    int h    = rest % H;
    int bt   = rest / H;
    int t    = bt & (T_ - 1);
    int b    = bt >> 11;

    float v = src[idx];
    float o;
    if (do_rope) {
        int dd = d & 63;
        float c = cosb[t * 64 + dd], s = sinb[t * 64 + dd];
        if (d < 64) { float v2 = src[idx + 64]; o = v * c - v2 * s; }
        else        { float v1 = src[idx - 64]; o = v * c + v1 * s; }
    } else {
        o = v;
    }
    o *= scale;
    __nv_bfloat16 hh = __float2bfloat16(o);
    size_t di = (((size_t)(b * H + h)) * T_ + t) * HD + d;
    dh[di] = hh;
    dl[di] = __float2bfloat16(o - __bfloat162float(hh));
}

__global__ void rope_all(const float* __restrict__ Qf, const float* __restrict__ Kf,
                         const float* __restrict__ Vf,
                         const float* __restrict__ cosb, const float* __restrict__ sinb,
                         __nv_bfloat16* __restrict__ Qh, __nv_bfloat16* __restrict__ Ql,
                         __nv_bfloat16* __restrict__ Kh, __nv_bfloat16* __restrict__ Kl,
                         __nv_bfloat16* __restrict__ Vh, __nv_bfloat16* __restrict__ Vl,
                         float qsc)
{
    int idx = blockIdx.x * 256 + threadIdx.x;
    if (idx < NQE) {
        rope_one(Qf, cosb, sinb, Qh, Ql, idx, NH, 1, qsc);
    } else if (idx < NQE + NKE) {
        rope_one(Kf, cosb, sinb, Kh, Kl, idx - NQE, NKV, 1, 1.0f);
    } else {
        rope_one(Vf, cosb, sinb, Vh, Vl, idx - NQE - NKE, NKV, 0, 1.0f);
    }
}

// =====================================================================
// Flash attention (causal, GQA). Br=64 (4 warps x 16 rows), Bc=64,
// single KV buffer, 2 CTAs per SM. mma issued term-major (chain spacing 2).
// =====================================================================
constexpr int AS       = 136;
constexpr int Q_H_OFF  = 0;
constexpr int Q_L_OFF  = 64 * AS;
constexpr int KV_OFF   = 2 * 64 * AS;
constexpr int ATTN_SMEM_BYTES = (2 * 64 * AS + 4 * 64 * AS) * 2;   // 104448

__global__ __launch_bounds__(128, 2) void attn_kernel(
    const __nv_bfloat16* __restrict__ Qh, const __nv_bfloat16* __restrict__ Ql,
    const __nv_bfloat16* __restrict__ Kh, const __nv_bfloat16* __restrict__ Kl,
    const __nv_bfloat16* __restrict__ Vh, const __nv_bfloat16* __restrict__ Vl,
    float* __restrict__ O)
{
    extern __shared__ __nv_bfloat16 sm[];
    const int tid  = threadIdx.x;
    const int lane = tid & 31;
    const int wid  = tid >> 5;                 // 0..3
    const int bh   = blockIdx.y;
    const int b    = bh >> 4, h = bh & 15;
    const int qi   = (int)gridDim.x - 1 - (int)blockIdx.x;   // heavy first
    const int qbase = qi * 64;
    const int kvi  = b * NKV + (h >> 2);

    const __nv_bfloat16* qh_g = Qh + ((size_t)bh * T_ + qbase) * HD;
    const __nv_bfloat16* ql_g = Ql + ((size_t)bh * T_ + qbase) * HD;
    const __nv_bfloat16* ks_g[4] = {
        Kh + (size_t)kvi * T_ * HD, Kl + (size_t)kvi * T_ * HD,
        Vh + (size_t)kvi * T_ * HD, Vl + (size_t)kvi * T_ * HD
    };

#pragma unroll
    for (int i = 0; i < 16; i++) {
        int c = i * 128 + tid;
        int split = c >> 10, cc = c & 1023;
        int row = cc >> 4, ch = cc & 15;
        const __nv_bfloat16* src = (split ? ql_g : qh_g) + row * HD + ch * 8;
        cpasync16(smem_u32(sm + (split ? Q_L_OFF : Q_H_OFF) + row * AS + ch * 8), src);
    }
    cpcommit();

    auto loadKV = [&](int j) {
        size_t gb = (size_t)j * 64 * HD;
#pragma unroll
        for (int i = 0; i < 32; i++) {
            int c = i * 128 + tid;
            int which = c >> 10, cc = c & 1023;
            int row = cc >> 4, ch = cc & 15;
            cpasync16(smem_u32(sm + KV_OFF + which * (64 * AS) + row * AS + ch * 8),
                      ks_g[which] + gb + row * HD + ch * 8);
        }
        cpcommit();
    };

    float m0 = -1e30f, m1 = -1e30f, l0 = 0.f, l1 = 0.f;
    float o[16][4];
#pragma unroll
    for (int i = 0; i < 16; i++)
#pragma unroll
        for (int j = 0; j < 4; j++) o[i][j] = 0.f;

    const int nj = qi + 1;
    const int rowbase = qbase + wid * 16;

    for (int j = 0; j < nj; j++) {
        loadKV(j);
        cpwait<0>();
        __syncthreads();

        // ---- S = Q K^T (exp2 domain), term-major mma ----
        float sacc[8][4];
#pragma unroll
        for (int i = 0; i < 8; i++)
#pragma unroll
            for (int jj = 0; jj < 4; jj++) sacc[i][jj] = 0.f;

#pragma unroll
        for (int ks = 0; ks < 8; ks++) {
            uint32_t qa[2][4];
            {
                int row = wid * 16 + (lane & 15);
                int col = ks * 16 + ((lane >> 4) << 3);
                ldsm4(qa[0], sm + Q_H_OFF + row * AS + col);
                ldsm4(qa[1], sm + Q_L_OFF + row * AS + col);
            }
#pragma unroll
            for (int nf2 = 0; nf2 < 4; nf2++) {
                uint32_t kh4[4], kl4[4];
                int krow = nf2 * 16 + (lane & 15);
                int kcol = ks * 16 + ((lane >> 4) << 3);
                ldsm4(kh4, sm + KV_OFF + krow * AS + kcol);
                ldsm4(kl4, sm + KV_OFF + 64 * AS + krow * AS + kcol);
                // term-major: both chains hit per term (spacing 2)
                mma_bf16(sacc[2 * nf2],     qa[0], kh4[0], kh4[2]);
                mma_bf16(sacc[2 * nf2 + 1], qa[0], kh4[1], kh4[3]);
                mma_bf16(sacc[2 * nf2],     qa[0], kl4[0], kl4[2]);
                mma_bf16(sacc[2 * nf2 + 1], qa[0], kl4[1], kl4[3]);
                mma_bf16(sacc[2 * nf2],     qa[1], kh4[0], kh4[2]);
                mma_bf16(sacc[2 * nf2 + 1], qa[1], kh4[1], kh4[3]);
            }
        }

        // ---- causal mask (diagonal tile only) ----
        const int kvb = j * 64;
        if (kvb + 63 > rowbase) {
            int r0 = rowbase + (lane >> 2), r1 = r0 + 8;
#pragma unroll
            for (int nf = 0; nf < 8; nf++) {
                int c0 = kvb + nf * 8 + (lane & 3) * 2;
                if (c0 > r0)     sacc[nf][0] = -1e30f;
                if (c0 + 1 > r0) sacc[nf][1] = -1e30f;
                if (c0 > r1)     sacc[nf][2] = -1e30f;
                if (c0 + 1 > r1) sacc[nf][3] = -1e30f;
            }
        }

        // ---- online softmax (base 2) ----
        float rm0 = -1e30f, rm1 = -1e30f;
#pragma unroll
        for (int nf = 0; nf < 8; nf++) {
            rm0 = fmaxf(rm0, fmaxf(sacc[nf][0], sacc[nf][1]));
            rm1 = fmaxf(rm1, fmaxf(sacc[nf][2], sacc[nf][3]));
        }
        rm0 = fmaxf(rm0, __shfl_xor_sync(0xffffffffu, rm0, 1));
        rm0 = fmaxf(rm0, __shfl_xor_sync(0xffffffffu, rm0, 2));
        rm1 = fmaxf(rm1, __shfl_xor_sync(0xffffffffu, rm1, 1));
        rm1 = fmaxf(rm1, __shfl_xor_sync(0xffffffffu, rm1, 2));
        float mn0 = fmaxf(m0, rm0), mn1 = fmaxf(m1, rm1);
        float corr0 = exp2f(m0 - mn0), corr1 = exp2f(m1 - mn1);
        m0 = mn0; m1 = mn1;

        float rs0 = 0.f, rs1 = 0.f;
#pragma unroll
        for (int nf = 0; nf < 8; nf++) {
            float p0 = exp2f(sacc[nf][0] - mn0);
            float p1 = exp2f(sacc[nf][1] - mn0);
            float p2 = exp2f(sacc[nf][2] - mn1);
            float p3 = exp2f(sacc[nf][3] - mn1);
            sacc[nf][0] = p0; sacc[nf][1] = p1; sacc[nf][2] = p2; sacc[nf][3] = p3;
            rs0 += p0 + p1; rs1 += p2 + p3;
        }
        l0 = l0 * corr0 + rs0;
        l1 = l1 * corr1 + rs1;
        if (__any_sync(0xffffffffu, (corr0 != 1.f) || (corr1 != 1.f))) {
#pragma unroll
            for (int df = 0; df < 16; df++) {
                o[df][0] *= corr0; o[df][1] *= corr0;
                o[df][2] *= corr1; o[df][3] *= corr1;
            }
        }

        // ---- pack P into bf16 hi/lo A-fragments ----
        uint32_t ph[4][4], pl[4][4];
#pragma unroll
        for (int kk = 0; kk < 4; kk++) {
            const float* A0 = sacc[2 * kk];
            const float* A1 = sacc[2 * kk + 1];
            split2(A0[0], A0[1], ph[kk][0], pl[kk][0]);
            split2(A0[2], A0[3], ph[kk][1], pl[kk][1]);
            split2(A1[0], A1[1], ph[kk][2], pl[kk][2]);
            split2(A1[2], A1[3], ph[kk][3], pl[kk][3]);
        }

        // ---- O += P V  (term-major mma) ----
        const int vb = KV_OFF + 2 * 64 * AS;
#pragma unroll
        for (int kk = 0; kk < 4; kk++) {
#pragma unroll
            for (int nf2 = 0; nf2 < 8; nf2++) {
                uint32_t vh4[4], vl4[4];
                int vrow = kk * 16 + (lane & 15);
                int vcol = nf2 * 16 + ((lane >> 4) << 3);
                ldsm4t(vh4, sm + vb + vrow * AS + vcol);
                ldsm4t(vl4, sm + vb + 64 * AS + vrow * AS + vcol);
                mma_bf16(o[2 * nf2],     ph[kk], vh4[0], vh4[1]);
                mma_bf16(o[2 * nf2 + 1], ph[kk], vh4[2], vh4[3]);
                mma_bf16(o[2 * nf2],     ph[kk], vl4[0], vl4[1]);
                mma_bf16(o[2 * nf2 + 1], ph[kk], vl4[2], vl4[3]);
                mma_bf16(o[2 * nf2],     pl[kk], vh4[0], vh4[1]);
                mma_bf16(o[2 * nf2 + 1], pl[kk], vh4[2], vh4[3]);
            }
        }
        __syncthreads();   // all reads done before next tile's cp.async overwrites
    }

    // ---- finalize ----
    l0 += __shfl_xor_sync(0xffffffffu, l0, 1);
    l0 += __shfl_xor_sync(0xffffffffu, l0, 2);
    l1 += __shfl_xor_sync(0xffffffffu, l1, 1);
    l1 += __shfl_xor_sync(0xffffffffu, l1, 2);
    float inv0 = 1.f / l0, inv1 = 1.f / l1;

    int r0 = rowbase + (lane >> 2);
    size_t base0 = ((size_t)b * T_ + r0) * HID + h * HD + (lane & 3) * 2;
    size_t base1 = base0 + (size_t)8 * HID;
#pragma unroll
    for (int df = 0; df < 16; df++) {
        *(float2*)(O + base0 + df * 8) = make_float2(o[df][0] * inv0, o[df][1] * inv0);
        *(float2*)(O + base1 + df * 8) = make_float2(o[df][2] * inv1, o[df][3] * inv1);
    }
}

// =====================================================================
// host launcher
// =====================================================================
extern "C" void kernel_launch(void* const* d_in, const int* in_sizes, int n_in,
                              void* d_out, int out_size)
{
    const float* x    = (const float*)d_in[0];
    const float* cosb = (const float*)d_in[1];
    const float* sinb = (const float*)d_in[2];
    const float* wq   = (const float*)d_in[3];
    const float* wk   = (const float*)d_in[4];
    const float* wv   = (const float*)d_in[5];
    const float* wo   = (const float*)d_in[6];

    float *Qf, *Kf, *Vf, *Octx;
    __nv_bfloat16 *Qh, *Ql, *Kh, *Kl, *Vh, *Vl;
    cudaGetSymbolAddress((void**)&Qf, g_Qf);
    cudaGetSymbolAddress((void**)&Kf, g_Kf);
    cudaGetSymbolAddress((void**)&Vf, g_Vf);
    cudaGetSymbolAddress((void**)&Octx, g_Octx);
    cudaGetSymbolAddress((void**)&Qh, g_Qh);
    cudaGetSymbolAddress((void**)&Ql, g_Ql);
    cudaGetSymbolAddress((void**)&Kh, g_Kh);
    cudaGetSymbolAddress((void**)&Kl, g_Kl);
    cudaGetSymbolAddress((void**)&Vh, g_Vh);
    cudaGetSymbolAddress((void**)&Vl, g_Vl);

    cudaFuncSetAttribute(attn_kernel, cudaFuncAttributeMaxDynamicSharedMemorySize,
                         ATTN_SMEM_BYTES);
    cudaFuncSetAttribute(gemm_bf16x3, cudaFuncAttributeMaxDynamicSharedMemorySize,
                         GEMM_SMEM_BYTES);

    const int M = B_ * T_;  // 4096
    float qsc = (1.0f / sqrtf((float)HD)) * 1.4426950408889634f;

    // launch order: attn at launch index 3 (ncu capture slot)
    gemm_bf16x3<<<dim3((NKV * HD) / 256, M / 128, 2), 512, GEMM_SMEM_BYTES>>>(
        x, wk, Kf, wv, Vf, M, NKV * HD, HID);                                    // 0: K+V fused
    gemm_bf16x3<<<dim3(HID / 256, M / 128, 1), 512, GEMM_SMEM_BYTES>>>(
        x, wq, Qf, wq, Qf, M, HID, HID);                                         // 1: Q
    rope_all<<<(NQE + 2 * NKE) / 256, 256>>>(Qf, Kf, Vf, cosb, sinb,
                                             Qh, Ql, Kh, Kl, Vh, Vl, qsc);       // 2
    attn_kernel<<<dim3(T_ / 64, B_ * NH), 128, ATTN_SMEM_BYTES>>>(
        Qh, Ql, Kh, Kl, Vh, Vl, Octx);                                           // 3  <- ncu
    gemm_bf16x3<<<dim3(HID / 256, M / 128, 1), 512, GEMM_SMEM_BYTES>>>(
        Octx, wo, (float*)d_out, wo, (float*)d_out, M, HID, HID);                // 4: O
}